// round 13
// baseline (speedup 1.0000x reference)
#include <cuda_runtime.h>
#include <cuda_bf16.h>
#include <math.h>

#define B_   16
#define L_   1024
#define H_   8
#define E_   64
#define D_   512
#define LF   513
#define NROW 8192            // B_*D_
#define VPITCH 514

// ---------------- device scratch (no cudaMalloc allowed) -------------------
__device__ __align__(16) __nv_bfloat16 g_Abh[16384 * 1536];  // im2col hi
__device__ __align__(16) __nv_bfloat16 g_Abl[16384 * 1536];  // im2col lo
__device__ __align__(16) __nv_bfloat16 g_Wbh[1024 * 1536];   // W hi [oc][r]
__device__ __align__(16) __nv_bfloat16 g_Wbl[1024 * 1536];   // W lo
__device__ __align__(16) float g_conv[16384 * 1024];         // conv out (a|g)+bias
// transposed spectra: [bh][x][e], contiguous in e
__device__ __align__(16) float g_qft_re[128 * LF * 64];
__device__ __align__(16) float g_qft_im[128 * LF * 64];
__device__ __align__(16) float g_kft_re[128 * LF * 64];
__device__ __align__(16) float g_kft_im[128 * LF * 64];
// v spectra: [row=bh*64+e][y], padded pitch 514
__device__ __align__(16) float g_vf_re[NROW * VPITCH];
__device__ __align__(16) float g_vf_im[NROW * VPITCH];
__device__ float  g_of_re[NROW * LF];
__device__ float  g_of_im[NROW * LF];
__device__ float2 g_tw[512];

// ---------------- packed f32x2 helpers ------------------------------------
__device__ __forceinline__ unsigned long long pk2(float lo, float hi) {
    unsigned long long r;
    asm("mov.b64 %0, {%1, %2};" : "=l"(r) : "f"(lo), "f"(hi));
    return r;
}
__device__ __forceinline__ void upk2(unsigned long long v, float& lo, float& hi) {
    asm("mov.b64 {%0, %1}, %2;" : "=f"(lo), "=f"(hi) : "l"(v));
}
__device__ __forceinline__ unsigned long long ffma2(unsigned long long a,
                                                    unsigned long long b,
                                                    unsigned long long c) {
    unsigned long long d;
    asm("fma.rn.f32x2 %0, %1, %2, %3;" : "=l"(d) : "l"(a), "l"(b), "l"(c));
    return d;
}
__device__ __forceinline__ unsigned long long neg2(unsigned long long a) {
    return a ^ 0x8000000080000000ULL;
}
__device__ __forceinline__ float sigmoidf_(float x) {
    return 1.0f / (1.0f + __expf(-x));
}
__device__ __forceinline__ int rowbase(int r) { return r * 66; }

// cp.async helpers
__device__ __forceinline__ void cp8(unsigned int dst, const void* src, int srcsize) {
    asm volatile("cp.async.ca.shared.global [%0], [%1], 8, %2;"
                 :: "r"(dst), "l"(src), "r"(srcsize));
}
__device__ __forceinline__ void cp16(unsigned int dst, const void* src, int srcsize) {
    asm volatile("cp.async.cg.shared.global [%0], [%1], 16, %2;"
                 :: "r"(dst), "l"(src), "r"(srcsize));
}
__device__ __forceinline__ void cp_commit() {
    asm volatile("cp.async.commit_group;");
}
template <int N>
__device__ __forceinline__ void cp_wait() {
    asm volatile("cp.async.wait_group %0;" :: "n"(N));
}

// ---------------- mma.sync helpers (sm_80-path; compiles on compute_103) ---
__device__ __forceinline__ void ldmx4(unsigned* r, unsigned a) {
    asm volatile("ldmatrix.sync.aligned.m8n8.x4.shared.b16 {%0,%1,%2,%3}, [%4];"
                 : "=r"(r[0]), "=r"(r[1]), "=r"(r[2]), "=r"(r[3]) : "r"(a));
}
__device__ __forceinline__ void mma_bf16(float* c, const unsigned* a,
                                         const unsigned* b) {
    asm volatile(
        "mma.sync.aligned.m16n8k16.row.col.f32.bf16.bf16.f32 "
        "{%0,%1,%2,%3}, {%4,%5,%6,%7}, {%8,%9}, {%0,%1,%2,%3};"
        : "+f"(c[0]), "+f"(c[1]), "+f"(c[2]), "+f"(c[3])
        : "r"(a[0]), "r"(a[1]), "r"(a[2]), "r"(a[3]), "r"(b[0]), "r"(b[1]));
}

// ---------------- init: split W to bf16 hi/lo + twiddle table --------------
__global__ __launch_bounds__(256) void init_kernel(const float* __restrict__ W) {
    int idx = blockIdx.x * 256 + threadIdx.x;     // exactly 1024*1536
    float w = W[idx];
    __nv_bfloat16 h = __float2bfloat16(w);
    g_Wbh[idx] = h;
    g_Wbl[idx] = __float2bfloat16(w - __bfloat162float(h));
    if (blockIdx.x == 0) {
        for (int j = threadIdx.x; j < 512; j += 256) {
            float s, c;
            sincosf(6.283185307179586f * (float)j * (1.0f / 1024.0f), &s, &c);
            g_tw[j] = make_float2(c, s);
        }
    }
}

// ---------------- im2col + bf16 split: q -> A[16384][1536] hi/lo -----------
__global__ __launch_bounds__(256) void im2col_kernel(const float* __restrict__ q) {
    int idx = blockIdx.x * 256 + threadIdx.x;     // exactly 16384*1536
    int row = idx / 1536, r = idx - row * 1536;
    int ic = r / 3, kw = r - ic * 3;
    int b = row >> 10, l = row & 1023;
    int ls = l + kw - 1;
    float v = 0.0f;
    if ((unsigned)ls < 1024u) v = q[((size_t)b * 1024 + ls) * 512 + ic];
    __nv_bfloat16 h = __float2bfloat16(v);
    g_Abh[idx] = h;
    g_Abl[idx] = __float2bfloat16(v - __bfloat162float(h));
}

// ---------------- Conv GEMM via mma.sync bf16 split-3 ----------------------
// D[128 l, 64 oc] = sum_k A[l,k]*W[oc,k]; K=1536 in 48 chunks of 32.
// 8 warps: 4(m) x 2(n), warp tile 32x32, mma m16n8k16, 3 terms hi/lo.
// smem per buf: Ah 8K | Al 8K | Bh 4K | Bl 4K = 24576 B; double = 49152 B.
// Swizzle: 16B seg' = seg ^ ((row>>1)&3), row stride 64B.
__global__ __launch_bounds__(256, 2) void conv_mma_kernel(
        const float* __restrict__ bias) {
    extern __shared__ char csmc[];
    unsigned sbase = (unsigned)__cvta_generic_to_shared(csmc);
    int tid = threadIdx.x;
    int wid = tid >> 5, lane = tid & 31;
    int n0 = blockIdx.x << 6;     // 16 n tiles
    int m0 = blockIdx.y << 7;     // 128 m tiles
    int wm = wid >> 1, wn = wid & 1;

    auto issue = [&](int ch, int buf) {
        unsigned tb = sbase + (unsigned)buf * 24576u;
        int k0 = ch << 5;
        const __nv_bfloat16* Ah = g_Abh + (size_t)m0 * 1536 + k0;
        const __nv_bfloat16* Al = g_Abl + (size_t)m0 * 1536 + k0;
#pragma unroll
        for (int o = 0; o < 2; o++) {
            int idx = tid + (o << 8);            // < 512
            int row = idx >> 2, seg = idx & 3;
            unsigned dst = tb + (unsigned)(row * 64 + ((seg ^ ((row >> 1) & 3)) << 4));
            cp16(dst,         Ah + (size_t)row * 1536 + seg * 8, 16);
            cp16(dst + 8192u, Al + (size_t)row * 1536 + seg * 8, 16);
        }
        const __nv_bfloat16* Bh = g_Wbh + (size_t)n0 * 1536 + k0;
        const __nv_bfloat16* Bl = g_Wbl + (size_t)n0 * 1536 + k0;
        {
            int row = tid >> 2, seg = tid & 3;   // 256 = 64 rows x 4 segs
            unsigned dst = tb + 16384u
                + (unsigned)(row * 64 + ((seg ^ ((row >> 1) & 3)) << 4));
            cp16(dst,         Bh + (size_t)row * 1536 + seg * 8, 16);
            cp16(dst + 4096u, Bl + (size_t)row * 1536 + seg * 8, 16);
        }
        cp_commit();
    };

    float acc[2][4][4];
#pragma unroll
    for (int mt = 0; mt < 2; mt++)
#pragma unroll
        for (int nt = 0; nt < 4; nt++)
#pragma unroll
            for (int i = 0; i < 4; i++) acc[mt][nt][i] = 0.0f;

    issue(0, 0);

    for (int ch = 0; ch < 48; ch++) {
        int buf = ch & 1;
        if (ch < 47) { issue(ch + 1, buf ^ 1); cp_wait<1>(); }
        else         { cp_wait<0>(); }
        __syncthreads();
        unsigned tb = sbase + (unsigned)buf * 24576u;

#pragma unroll
        for (int s = 0; s < 2; s++) {
            unsigned ah[2][4], al[2][4];
#pragma unroll
            for (int mt = 0; mt < 2; mt++) {
                int row = (wm << 5) + (mt << 4) + (lane & 15);
                int seg = (s << 1) + (lane >> 4);
                unsigned a = tb + (unsigned)(row * 64 + ((seg ^ ((row >> 1) & 3)) << 4));
                ldmx4(ah[mt], a);
                ldmx4(al[mt], a + 8192u);
            }
            unsigned bh[4][2], bl[4][2];
#pragma unroll
            for (int np = 0; np < 2; np++) {
                int row = (wn << 5) + (np << 4) + ((lane >> 4) << 3) + (lane & 7);
                int seg = (s << 1) + ((lane >> 3) & 1);
                unsigned a = tb + 16384u
                    + (unsigned)(row * 64 + ((seg ^ ((row >> 1) & 3)) << 4));
                unsigned r[4];
                ldmx4(r, a);
                bh[np * 2][0] = r[0]; bh[np * 2][1] = r[1];
                bh[np * 2 + 1][0] = r[2]; bh[np * 2 + 1][1] = r[3];
                ldmx4(r, a + 4096u);
                bl[np * 2][0] = r[0]; bl[np * 2][1] = r[1];
                bl[np * 2 + 1][0] = r[2]; bl[np * 2 + 1][1] = r[3];
            }
#pragma unroll
            for (int mt = 0; mt < 2; mt++)
#pragma unroll
                for (int nt = 0; nt < 4; nt++) {
                    mma_bf16(acc[mt][nt], ah[mt], bh[nt]);
                    mma_bf16(acc[mt][nt], ah[mt], bl[nt]);
                    mma_bf16(acc[mt][nt], al[mt], bh[nt]);
                }
        }
        __syncthreads();
    }

    // epilogue: C frag (c0,c1)=(row, col..col+1), (c2,c3)=(row+8, ..)
    int r0 = m0 + (wm << 5) + (lane >> 2);
    int c0 = n0 + (wn << 5) + ((lane & 3) << 1);
#pragma unroll
    for (int mt = 0; mt < 2; mt++)
#pragma unroll
        for (int nt = 0; nt < 4; nt++) {
            int row = r0 + (mt << 4);
            int col = c0 + (nt << 3);
            float b0v = bias[col], b1v = bias[col + 1];
            *(float2*)(g_conv + (size_t)row * 1024 + col) =
                make_float2(acc[mt][nt][0] + b0v, acc[mt][nt][1] + b1v);
            *(float2*)(g_conv + (size_t)(row + 8) * 1024 + col) =
                make_float2(acc[mt][nt][2] + b0v, acc[mt][nt][3] + b1v);
        }
}

// ---------------- 1024-pt radix-2 Stockham (DIF, natural order) ------------
__device__ __forceinline__ void fft1024_shared(float2* bufA, float2* bufB,
                                               float sgn, int tid) {
    float2* src = bufA;
    float2* dst = bufB;
    int m = 1;
#pragma unroll
    for (int stage = 0; stage < 10; stage++) {
#pragma unroll
        for (int u = 0; u < 2; u++) {
            int idx = tid + (u << 8);
            float2 c0 = src[idx];
            float2 c1 = src[idx + 512];
            int k = idx & (m - 1);
            int o = idx + (idx - k);
            float2 w = g_tw[idx - k];
            float wy = w.y * sgn;
            float trx = c0.x - c1.x, trY = c0.y - c1.y;
            dst[o]     = make_float2(c0.x + c1.x, c0.y + c1.y);
            dst[o + m] = make_float2(w.x * trx - wy * trY, w.x * trY + wy * trx);
        }
        __syncthreads();
        float2* t = src; src = dst; dst = t;
        m <<= 1;
    }
}

// rffts of k (-> transposed) and v (-> padded rows): blockIdx.y 0=k, 1=v
__global__ __launch_bounds__(256) void rfft_kv_kernel(const float* __restrict__ kin,
                                                      const float* __restrict__ vin) {
    __shared__ float2 bufA[1024];
    __shared__ float2 bufB[1024];
    int row = blockIdx.x, tid = threadIdx.x;
    int isv = blockIdx.y;
    const float* in = isv ? vin : kin;
    const float* p = in + (size_t)(row >> 9) * 524288 + (row & 511);
    for (int i = tid; i < 1024; i += 256)
        bufA[i] = make_float2(p[(size_t)i * 512], 0.0f);
    __syncthreads();
    fft1024_shared(bufA, bufB, -1.0f, tid);
    if (isv) {
        size_t ob = (size_t)row * VPITCH;
        for (int i = tid; i < 513; i += 256) {
            float2 vv = bufA[i];
            g_vf_re[ob + i] = vv.x * 0.03125f;
            g_vf_im[ob + i] = vv.y * 0.03125f;
        }
    } else {
        int bh = row >> 6, e = row & 63;
        size_t ob = (size_t)bh * LF * 64 + e;
        for (int i = tid; i < 513; i += 256) {
            float2 vv = bufA[i];
            g_kft_re[ob + (size_t)i * 64] = vv.x * 0.03125f;
            g_kft_im[ob + (size_t)i * 64] = vv.y * 0.03125f;
        }
    }
}

// rfft of q with fused GLU load: q2[l] = a[l]*sigmoid(g[l]) from g_conv
__global__ __launch_bounds__(256) void rfft_q_kernel() {
    __shared__ float2 bufA[1024];
    __shared__ float2 bufB[1024];
    int row = blockIdx.x, tid = threadIdx.x;   // row = b*512 + c
    int b = row >> 9, c = row & 511;
    const float* p = g_conv + (size_t)b * 1024 * 1024 + c;
    for (int i = tid; i < 1024; i += 256) {
        float a = p[(size_t)i * 1024];
        float g = p[(size_t)i * 1024 + 512];
        bufA[i] = make_float2(a * sigmoidf_(g), 0.0f);
    }
    __syncthreads();
    fft1024_shared(bufA, bufB, -1.0f, tid);
    int bh = row >> 6, e = row & 63;
    size_t ob = (size_t)bh * LF * 64 + e;
    for (int i = tid; i < 513; i += 256) {
        float2 vv = bufA[i];
        g_qft_re[ob + (size_t)i * 64] = vv.x * 0.03125f;
        g_qft_im[ob + (size_t)i * 64] = vv.y * 0.03125f;
    }
}

// ---------------- fused frequency attention: 32-x tile, occ-2 --------------
__global__ __launch_bounds__(256, 2) void attn_kernel() {
    extern __shared__ float sm[];
    float* Qre = sm;                  // [32 x][64 e] pitch 66
    float* Qim = sm + 2112;
    float* Kre = sm + 4224;           // [64 y][64 e] pitch 66
    float* Kim = sm + 8448;
    float* Vre = sm + 12672;          // [64 e][64 y] pitch 66
    float* Vim = sm + 16896;
    float* Tre = sm + 21120;          // [32 x][64 y] pitch 66
    float* Tim = sm + 23232;

    int bh  = blockIdx.y;
    int x0  = blockIdx.x << 5;
    int tid = threadIdx.x;
    int tx  = tid & 15, ty = tid >> 4;
    size_t tbase = (size_t)bh * LF * 64;
    size_t obase = (size_t)bh * 64 * LF;

    unsigned int sQre = (unsigned int)__cvta_generic_to_shared(Qre);
    unsigned int sQim = (unsigned int)__cvta_generic_to_shared(Qim);
    unsigned int sKre = (unsigned int)__cvta_generic_to_shared(Kre);
    unsigned int sKim = (unsigned int)__cvta_generic_to_shared(Kim);
    unsigned int sVre = (unsigned int)__cvta_generic_to_shared(Vre);
    unsigned int sVim = (unsigned int)__cvta_generic_to_shared(Vim);

    {
#pragma unroll
        for (int o = 0; o < 4; o++) {
            int flat = tid + (o << 8);
            int r = flat >> 5, p = flat & 31;
            int valid = (x0 + r) < 513;
            const float* sre = g_qft_re + tbase + (size_t)(x0 + r) * 64 + 2 * p;
            const float* sim = g_qft_im + tbase + (size_t)(x0 + r) * 64 + 2 * p;
            unsigned int d = (unsigned int)((r * 66 + 2 * p) * 4);
            cp8(sQre + d, valid ? sre : g_qft_re, valid ? 8 : 0);
            cp8(sQim + d, valid ? sim : g_qft_im, valid ? 8 : 0);
        }
#pragma unroll
        for (int o = 0; o < 8; o++) {
            int flat = tid + (o << 8);
            int r = flat >> 5, p = flat & 31;
            const float* sre = g_kft_re + tbase + (size_t)r * 64 + 2 * p;
            const float* sim = g_kft_im + tbase + (size_t)r * 64 + 2 * p;
            unsigned int d = (unsigned int)((r * 66 + 2 * p) * 4);
            cp8(sKre + d, sre, 8);
            cp8(sKim + d, sim, 8);
        }
        cp_commit();
#pragma unroll
        for (int o = 0; o < 8; o++) {
            int flat = tid + (o << 8);
            int r = flat >> 5, p = flat & 31;
            const float* sre = g_vf_re + (size_t)(bh * 64 + r) * VPITCH + 2 * p;
            const float* sim = g_vf_im + (size_t)(bh * 64 + r) * VPITCH + 2 * p;
            unsigned int d = (unsigned int)((r * 66 + 2 * p) * 4);
            cp8(sVre + d, sre, 8);
            cp8(sVim + d, sim, 8);
        }
        cp_commit();
    }

    int qb[2], kb[4];
#pragma unroll
    for (int i = 0; i < 2; i++) qb[i] = rowbase((ty << 1) + i);
#pragma unroll
    for (int j = 0; j < 4; j++) kb[j] = rowbase(tx + (j << 4));

    unsigned long long ore_p[2][4], oim_p[2][4];
#pragma unroll
    for (int i = 0; i < 2; i++)
#pragma unroll
        for (int j = 0; j < 4; j++) { ore_p[i][j] = 0ull; oim_p[i][j] = 0ull; }
    float Dacc[2] = {};

    cp_wait<1>();
    __syncthreads();

    for (int yt = 0; yt < 9; yt++) {
        unsigned long long sre_p[2][4], sim_p[2][4];
#pragma unroll
        for (int i = 0; i < 2; i++)
#pragma unroll
            for (int j = 0; j < 4; j++) { sre_p[i][j] = 0ull; sim_p[i][j] = 0ull; }

        for (int e2 = 0; e2 < 32; e2++) {
            unsigned long long qr[2], qi[2], qrn[2], kr[4], ki[4];
            int off = e2 << 1;
#pragma unroll
            for (int i = 0; i < 2; i++) {
                qr[i] = *(const unsigned long long*)(Qre + qb[i] + off);
                qi[i] = *(const unsigned long long*)(Qim + qb[i] + off);
                qrn[i] = neg2(qr[i]);
            }
#pragma unroll
            for (int j = 0; j < 4; j++) {
                kr[j] = *(const unsigned long long*)(Kre + kb[j] + off);
                ki[j] = *(const unsigned long long*)(Kim + kb[j] + off);
            }
#pragma unroll
            for (int i = 0; i < 2; i++)
#pragma unroll
                for (int j = 0; j < 4; j++) {
                    sre_p[i][j] = ffma2(qr[i],  kr[j], sre_p[i][j]);
                    sre_p[i][j] = ffma2(qi[i],  ki[j], sre_p[i][j]);
                    sim_p[i][j] = ffma2(qi[i],  kr[j], sim_p[i][j]);
                    sim_p[i][j] = ffma2(qrn[i], ki[j], sim_p[i][j]);
                }
        }
        __syncthreads();

        if (yt < 8) {
            int y0n = (yt + 1) << 6;
#pragma unroll
            for (int o = 0; o < 8; o++) {
                int flat = tid + (o << 8);
                int r = flat >> 5, p = flat & 31;
                int valid = (y0n + r) < 513;
                const float* sre = g_kft_re + tbase + (size_t)(y0n + r) * 64 + 2 * p;
                const float* sim = g_kft_im + tbase + (size_t)(y0n + r) * 64 + 2 * p;
                unsigned int d = (unsigned int)((r * 66 + 2 * p) * 4);
                cp8(sKre + d, valid ? sre : g_kft_re, valid ? 8 : 0);
                cp8(sKim + d, valid ? sim : g_kft_im, valid ? 8 : 0);
            }
            cp_commit();
        }

#pragma unroll
        for (int i = 0; i < 2; i++)
#pragma unroll
            for (int j = 0; j < 4; j++) {
                float a0, a1, b0, b1;
                upk2(sre_p[i][j], a0, a1);
                upk2(sim_p[i][j], b0, b1);
                float sr = (a0 + a1) * 0.125f;
                float si = (b0 + b1) * 0.125f;
                float mg = sqrtf(sr * sr + si * si);
                float w  = 1.0f + sigmoidf_(mg);
                Dacc[i] += mg * w;
                int a = qb[i] + tx + (j << 4);
                Tre[a] = sr * w;
                Tim[a] = si * w;
            }

        if (yt < 8) cp_wait<1>(); else cp_wait<0>();
        __syncthreads();

        for (int y2 = 0; y2 < 32; y2++) {
            unsigned long long tr[2], ti[2], tin[2], vr[4], vi[4];
            int off = y2 << 1;
#pragma unroll
            for (int i = 0; i < 2; i++) {
                tr[i] = *(const unsigned long long*)(Tre + qb[i] + off);
                ti[i] = *(const unsigned long long*)(Tim + qb[i] + off);
                tin[i] = neg2(ti[i]);
            }
#pragma unroll
            for (int j = 0; j < 4; j++) {
                vr[j] = *(const unsigned long long*)(Vre + kb[j] + off);
                vi[j] = *(const unsigned long long*)(Vim + kb[j] + off);
            }
#pragma unroll
            for (int i = 0; i < 2; i++)
#pragma unroll
                for (int j = 0; j < 4; j++) {
                    ore_p[i][j] = ffma2(tr[i],  vr[j], ore_p[i][j]);
                    ore_p[i][j] = ffma2(tin[i], vi[j], ore_p[i][j]);
                    oim_p[i][j] = ffma2(tr[i],  vi[j], oim_p[i][j]);
                    oim_p[i][j] = ffma2(ti[i],  vr[j], oim_p[i][j]);
                }
        }
        __syncthreads();

        if (yt < 8) {
            int y0n = (yt + 1) << 6;
#pragma unroll
            for (int o = 0; o < 8; o++) {
                int flat = tid + (o << 8);
                int r = flat >> 5, p = flat & 31;
                int rem = 513 - (y0n + 2 * p);
                int sz = rem >= 2 ? 8 : (rem == 1 ? 4 : 0);
                const float* sre = g_vf_re + (size_t)(bh * 64 + r) * VPITCH + y0n + 2 * p;
                const float* sim = g_vf_im + (size_t)(bh * 64 + r) * VPITCH + y0n + 2 * p;
                unsigned int d = (unsigned int)((r * 66 + 2 * p) * 4);
                cp8(sVre + d, sre, sz);
                cp8(sVim + d, sim, sz);
            }
            cp_commit();
            cp_wait<1>();
            __syncthreads();
        }
    }

#pragma unroll
    for (int i = 0; i < 2; i++) {
        float dsum = Dacc[i];
        dsum += __shfl_xor_sync(0xffffffffu, dsum, 1);
        dsum += __shfl_xor_sync(0xffffffffu, dsum, 2);
        dsum += __shfl_xor_sync(0xffffffffu, dsum, 4);
        dsum += __shfl_xor_sync(0xffffffffu, dsum, 8);
        Dacc[i] = 1.0f / fmaxf(dsum, 1e-12f);
    }
#pragma unroll
    for (int i = 0; i < 2; i++) {
        int x = x0 + (ty << 1) + i;
        if (x < 513) {
#pragma unroll
            for (int j = 0; j < 4; j++) {
                int e = tx + (j << 4);
                float a0, a1, b0, b1;
                upk2(ore_p[i][j], a0, a1);
                upk2(oim_p[i][j], b0, b1);
                g_of_re[obase + (size_t)e * 513 + x] = (a0 + a1) * Dacc[i];
                g_of_im[obase + (size_t)e * 513 + x] = (b0 + b1) * Dacc[i];
            }
        }
    }
}

// ---------------- irfft (ortho) + scatter to out[b,l,h,e] ------------------
__global__ __launch_bounds__(256) void irfft_kernel(float* __restrict__ out) {
    __shared__ float2 bufA[1024];
    __shared__ float2 bufB[1024];
    int row = blockIdx.x, tid = threadIdx.x;
    const float* pr = g_of_re + (size_t)row * 513;
    const float* pi = g_of_im + (size_t)row * 513;
    for (int i = tid; i < 1024; i += 256) {
        float re, im;
        if (i < 513) { re = pr[i];        im =  pi[i]; }
        else         { re = pr[1024 - i]; im = -pi[1024 - i]; }
        bufA[i] = make_float2(re, im);
    }
    __syncthreads();
    fft1024_shared(bufA, bufB, 1.0f, tid);
    int b = row >> 9, c = row & 511;
    float* po = out + (size_t)b * 524288 + c;
    for (int i = tid; i < 1024; i += 256)
        po[(size_t)i * 512] = bufA[i].x * 0.03125f;
}

// ---------------- launch ---------------------------------------------------
extern "C" void kernel_launch(void* const* d_in, const int* in_sizes, int n_in,
                              void* d_out, int out_size) {
    const float* q    = (const float*)d_in[0];
    const float* k    = (const float*)d_in[1];
    const float* v    = (const float*)d_in[2];
    const float* W    = (const float*)d_in[3];
    const float* bias = (const float*)d_in[4];
    float* out = (float*)d_out;

    const int attn_smem = 25344 * (int)sizeof(float);       // 101376 B
    cudaFuncSetAttribute(attn_kernel,
                         cudaFuncAttributeMaxDynamicSharedMemorySize, attn_smem);
    const int conv_smem = 49152;                            // 2 x 24576 B
    cudaFuncSetAttribute(conv_mma_kernel,
                         cudaFuncAttributeMaxDynamicSharedMemorySize, conv_smem);

    init_kernel<<<6144, 256>>>(W);                          // 1024*1536 / 256
    im2col_kernel<<<98304, 256>>>(q);                       // 16384*1536 / 256
    rfft_kv_kernel<<<dim3(NROW, 2), 256>>>(k, v);
    conv_mma_kernel<<<dim3(16, 128), 256, conv_smem>>>(bias);   // ncu slot (4th)
    rfft_q_kernel<<<NROW, 256>>>();
    attn_kernel<<<dim3(17, 128), 256, attn_smem>>>();
    irfft_kernel<<<NROW, 256>>>(out);
}

// round 15
// speedup vs baseline: 1.3299x; 1.3299x over previous
#include <cuda_runtime.h>
#include <cuda_bf16.h>
#include <math.h>

#define LF    513
#define NROW  8192
#define QK_SZ (128 * 513 * 64)
#define V_SZ  (8192 * 576)

// ---------------- device scratch -------------------------------------------
__device__ __align__(16) __nv_bfloat16 g_Abh[16384 * 1536];
__device__ __align__(16) __nv_bfloat16 g_Abl[16384 * 1536];
__device__ __align__(16) __nv_bfloat16 g_Wbh[1024 * 1536];
__device__ __align__(16) __nv_bfloat16 g_Wbl[1024 * 1536];
__device__ __align__(16) float g_conv[16384 * 1024];
// spectra bf16 split: comp 0=re_hi 1=re_lo 2=im_hi 3=im_lo
__device__ __align__(16) __nv_bfloat16 g_qsp[4][QK_SZ];   // [bh][x][e]
__device__ __align__(16) __nv_bfloat16 g_ksp[4][QK_SZ];   // [bh][y][e]
__device__ __align__(16) __nv_bfloat16 g_vsp[4][V_SZ];    // [bh*64+e][y] p576
__device__ float  g_of_re[NROW * LF];
__device__ float  g_of_im[NROW * LF];
__device__ float2 g_tw[512];

// ---------------- helpers --------------------------------------------------
__device__ __forceinline__ float sigmoidf_(float x) {
    return 1.0f / (1.0f + __expf(-x));
}
__device__ __forceinline__ unsigned pkbf(float lo, float hi) {
    unsigned r;
    asm("cvt.rn.bf16x2.f32 %0, %1, %2;" : "=r"(r) : "f"(hi), "f"(lo));
    return r;
}
__device__ __forceinline__ void split2(float a, float b, unsigned& h, unsigned& l) {
    h = pkbf(a, b);
    float ra = a - __uint_as_float(h << 16);
    float rb = b - __uint_as_float(h & 0xFFFF0000u);
    l = pkbf(ra, rb);
}
__device__ __forceinline__ void cp16(unsigned dst, const void* src, int sz) {
    asm volatile("cp.async.cg.shared.global [%0], [%1], 16, %2;"
                 :: "r"(dst), "l"(src), "r"(sz));
}
__device__ __forceinline__ void cp_commit() {
    asm volatile("cp.async.commit_group;");
}
template <int N>
__device__ __forceinline__ void cp_wait() {
    asm volatile("cp.async.wait_group %0;" :: "n"(N));
}
__device__ __forceinline__ void ldmx4(unsigned* r, unsigned a) {
    asm volatile("ldmatrix.sync.aligned.m8n8.x4.shared.b16 {%0,%1,%2,%3}, [%4];"
                 : "=r"(r[0]), "=r"(r[1]), "=r"(r[2]), "=r"(r[3]) : "r"(a));
}
__device__ __forceinline__ void mma4(float* c, const unsigned* a,
                                     unsigned b0, unsigned b1) {
    asm volatile(
        "mma.sync.aligned.m16n8k16.row.col.f32.bf16.bf16.f32 "
        "{%0,%1,%2,%3}, {%4,%5,%6,%7}, {%8,%9}, {%0,%1,%2,%3};"
        : "+f"(c[0]), "+f"(c[1]), "+f"(c[2]), "+f"(c[3])
        : "r"(a[0]), "r"(a[1]), "r"(a[2]), "r"(a[3]), "r"(b0), "r"(b1));
}

// ---------------- init: W split + im2col split + twiddles ------------------
__global__ __launch_bounds__(256) void init_all_kernel(const float* __restrict__ W,
                                                       const float* __restrict__ q) {
    long long idx = (long long)blockIdx.x * 256 + threadIdx.x;
    if (idx < 1024 * 1536) {
        float w = W[idx];
        __nv_bfloat16 h = __float2bfloat16(w);
        g_Wbh[idx] = h;
        g_Wbl[idx] = __float2bfloat16(w - __bfloat162float(h));
    } else {
        long long a = idx - 1024 * 1536;
        int row = (int)(a / 1536), r = (int)(a - (long long)row * 1536);
        int ic = r / 3, kw = r - ic * 3;
        int b = row >> 10, l = row & 1023;
        int ls = l + kw - 1;
        float v = 0.0f;
        if ((unsigned)ls < 1024u) v = q[((size_t)b * 1024 + ls) * 512 + ic];
        __nv_bfloat16 h = __float2bfloat16(v);
        g_Abh[a] = h;
        g_Abl[a] = __float2bfloat16(v - __bfloat162float(h));
    }
    if (blockIdx.x == 0) {
        for (int j = threadIdx.x; j < 512; j += 256) {
            float s, c;
            sincosf(6.283185307179586f * (float)j * (1.0f / 1024.0f), &s, &c);
            g_tw[j] = make_float2(c, s);
        }
    }
}

// ---------------- Conv GEMM via mma.sync bf16 split-3 (proven R11) ---------
__global__ __launch_bounds__(256, 2) void conv_mma_kernel(
        const float* __restrict__ bias) {
    extern __shared__ char csmc[];
    unsigned sbase = (unsigned)__cvta_generic_to_shared(csmc);
    int tid = threadIdx.x;
    int wid = tid >> 5, lane = tid & 31;
    int n0 = blockIdx.x << 6;
    int m0 = blockIdx.y << 7;
    int wm = wid >> 1, wn = wid & 1;

    auto issue = [&](int ch, int buf) {
        unsigned tb = sbase + (unsigned)buf * 24576u;
        int k0 = ch << 5;
        const __nv_bfloat16* Ah = g_Abh + (size_t)m0 * 1536 + k0;
        const __nv_bfloat16* Al = g_Abl + (size_t)m0 * 1536 + k0;
#pragma unroll
        for (int o = 0; o < 2; o++) {
            int idx = tid + (o << 8);
            int row = idx >> 2, seg = idx & 3;
            unsigned dst = tb + (unsigned)(row * 64 + ((seg ^ ((row >> 1) & 3)) << 4));
            cp16(dst,         Ah + (size_t)row * 1536 + seg * 8, 16);
            cp16(dst + 8192u, Al + (size_t)row * 1536 + seg * 8, 16);
        }
        const __nv_bfloat16* Bh = g_Wbh + (size_t)n0 * 1536 + k0;
        const __nv_bfloat16* Bl = g_Wbl + (size_t)n0 * 1536 + k0;
        {
            int row = tid >> 2, seg = tid & 3;
            unsigned dst = tb + 16384u
                + (unsigned)(row * 64 + ((seg ^ ((row >> 1) & 3)) << 4));
            cp16(dst,         Bh + (size_t)row * 1536 + seg * 8, 16);
            cp16(dst + 4096u, Bl + (size_t)row * 1536 + seg * 8, 16);
        }
        cp_commit();
    };

    float acc[2][4][4];
#pragma unroll
    for (int mt = 0; mt < 2; mt++)
#pragma unroll
        for (int nt = 0; nt < 4; nt++)
#pragma unroll
            for (int i = 0; i < 4; i++) acc[mt][nt][i] = 0.0f;

    issue(0, 0);

    for (int ch = 0; ch < 48; ch++) {
        int buf = ch & 1;
        if (ch < 47) { issue(ch + 1, buf ^ 1); cp_wait<1>(); }
        else         { cp_wait<0>(); }
        __syncthreads();
        unsigned tb = sbase + (unsigned)buf * 24576u;

#pragma unroll
        for (int s = 0; s < 2; s++) {
            unsigned ah[2][4], al[2][4];
#pragma unroll
            for (int mt = 0; mt < 2; mt++) {
                int row = (wm << 5) + (mt << 4) + (lane & 15);
                int seg = (s << 1) + (lane >> 4);
                unsigned a = tb + (unsigned)(row * 64 + ((seg ^ ((row >> 1) & 3)) << 4));
                ldmx4(ah[mt], a);
                ldmx4(al[mt], a + 8192u);
            }
            unsigned bh[4][2], bl[4][2];
#pragma unroll
            for (int np = 0; np < 2; np++) {
                int row = (wn << 5) + (np << 4) + ((lane >> 4) << 3) + (lane & 7);
                int seg = (s << 1) + ((lane >> 3) & 1);
                unsigned a = tb + 16384u
                    + (unsigned)(row * 64 + ((seg ^ ((row >> 1) & 3)) << 4));
                unsigned r[4];
                ldmx4(r, a);
                bh[np * 2][0] = r[0]; bh[np * 2][1] = r[1];
                bh[np * 2 + 1][0] = r[2]; bh[np * 2 + 1][1] = r[3];
                ldmx4(r, a + 4096u);
                bl[np * 2][0] = r[0]; bl[np * 2][1] = r[1];
                bl[np * 2 + 1][0] = r[2]; bl[np * 2 + 1][1] = r[3];
            }
#pragma unroll
            for (int mt = 0; mt < 2; mt++)
#pragma unroll
                for (int nt = 0; nt < 4; nt++) {
                    mma4(acc[mt][nt], ah[mt], bh[nt][0], bh[nt][1]);
                    mma4(acc[mt][nt], ah[mt], bl[nt][0], bl[nt][1]);
                    mma4(acc[mt][nt], al[mt], bh[nt][0], bh[nt][1]);
                }
        }
        __syncthreads();
    }

    int r0 = m0 + (wm << 5) + (lane >> 2);
    int c0 = n0 + (wn << 5) + ((lane & 3) << 1);
#pragma unroll
    for (int mt = 0; mt < 2; mt++)
#pragma unroll
        for (int nt = 0; nt < 4; nt++) {
            int row = r0 + (mt << 4);
            int col = c0 + (nt << 3);
            float b0v = bias[col], b1v = bias[col + 1];
            *(float2*)(g_conv + (size_t)row * 1024 + col) =
                make_float2(acc[mt][nt][0] + b0v, acc[mt][nt][1] + b1v);
            *(float2*)(g_conv + (size_t)(row + 8) * 1024 + col) =
                make_float2(acc[mt][nt][2] + b0v, acc[mt][nt][3] + b1v);
        }
}

// ---------------- 1024-pt radix-2 Stockham ---------------------------------
__device__ __forceinline__ void fft1024_shared(float2* bufA, float2* bufB,
                                               float sgn, int tid) {
    float2* src = bufA;
    float2* dst = bufB;
    int m = 1;
#pragma unroll
    for (int stage = 0; stage < 10; stage++) {
#pragma unroll
        for (int u = 0; u < 2; u++) {
            int idx = tid + (u << 8);
            float2 c0 = src[idx];
            float2 c1 = src[idx + 512];
            int k = idx & (m - 1);
            int o = idx + (idx - k);
            float2 w = g_tw[idx - k];
            float wy = w.y * sgn;
            float trx = c0.x - c1.x, trY = c0.y - c1.y;
            dst[o]     = make_float2(c0.x + c1.x, c0.y + c1.y);
            dst[o + m] = make_float2(w.x * trx - wy * trY, w.x * trY + wy * trx);
        }
        __syncthreads();
        float2* t = src; src = dst; dst = t;
        m <<= 1;
    }
}

// all rffts: blockIdx.y 0=q (GLU from g_conv), 1=k, 2=v
__global__ __launch_bounds__(256) void rfft_all_kernel(const float* __restrict__ kin,
                                                       const float* __restrict__ vin) {
    __shared__ float2 bufA[1024];
    __shared__ float2 bufB[1024];
    int row = blockIdx.x, tid = threadIdx.x;
    int which = blockIdx.y;
    if (which == 0) {
        int b = row >> 9, c = row & 511;
        const float* p = g_conv + (size_t)b * 1024 * 1024 + c;
        for (int i = tid; i < 1024; i += 256) {
            float a = p[(size_t)i * 1024];
            float g = p[(size_t)i * 1024 + 512];
            bufA[i] = make_float2(a * sigmoidf_(g), 0.0f);
        }
    } else {
        const float* in = (which == 2) ? vin : kin;
        const float* p = in + (size_t)(row >> 9) * 524288 + (row & 511);
        for (int i = tid; i < 1024; i += 256)
            bufA[i] = make_float2(p[(size_t)i * 512], 0.0f);
    }
    __syncthreads();
    fft1024_shared(bufA, bufB, -1.0f, tid);
    int bh = row >> 6, e = row & 63;
    if (which == 2) {
        size_t ob = (size_t)row * 576;
        for (int i = tid; i < 576; i += 256) {
            float re = 0.0f, im = 0.0f;
            if (i < 513) { re = bufA[i].x * 0.03125f; im = bufA[i].y * 0.03125f; }
            __nv_bfloat16 hr = __float2bfloat16(re);
            __nv_bfloat16 hi = __float2bfloat16(im);
            g_vsp[0][ob + i] = hr;
            g_vsp[1][ob + i] = __float2bfloat16(re - __bfloat162float(hr));
            g_vsp[2][ob + i] = hi;
            g_vsp[3][ob + i] = __float2bfloat16(im - __bfloat162float(hi));
        }
    } else {
        size_t ob = (size_t)bh * 513 * 64 + e;
        for (int i = tid; i < 513; i += 256) {
            float re = bufA[i].x * 0.03125f;
            float im = bufA[i].y * 0.03125f;
            __nv_bfloat16 hr = __float2bfloat16(re);
            __nv_bfloat16 hi = __float2bfloat16(im);
            size_t a = ob + (size_t)i * 64;
            if (which == 1) {
                g_ksp[0][a] = hr;
                g_ksp[1][a] = __float2bfloat16(re - __bfloat162float(hr));
                g_ksp[2][a] = hi;
                g_ksp[3][a] = __float2bfloat16(im - __bfloat162float(hi));
            } else {
                g_qsp[0][a] = hr;
                g_qsp[1][a] = __float2bfloat16(re - __bfloat162float(hr));
                g_qsp[2][a] = hi;
                g_qsp[3][a] = __float2bfloat16(im - __bfloat162float(hi));
            }
        }
    }
}

// ---------------- tensor-core frequency attention --------------------------
// 128 thr = 4 warps x m16. x-tile 64, y-tile 64 x 9. T register-resident.
// smem: Q 32K | K 32K | V 32K (4 comps x 8K each, 128B rows, seg^=(row&7)).
__global__ __launch_bounds__(128, 2) void attn_kernel() {
    extern __shared__ char asmem[];
    unsigned sb = (unsigned)__cvta_generic_to_shared(asmem);
    int tid = threadIdx.x;
    int w = tid >> 5, lane = tid & 31;
    int bh = blockIdx.y;
    int x0 = blockIdx.x << 6;
    size_t qkb = (size_t)bh * 513 * 64;
    size_t vb  = (size_t)bh * 64 * 576;
    size_t obase = (size_t)bh * 64 * 513;

    // Q load (once)
#pragma unroll
    for (int comp = 0; comp < 4; comp++)
#pragma unroll
        for (int i = 0; i < 4; i++) {
            int idx = tid + (i << 7);
            int row = idx >> 3, seg = idx & 7;
            int ok = (x0 + row) < 513;
            const __nv_bfloat16* s = g_qsp[comp] + qkb + (size_t)(x0 + row) * 64 + seg * 8;
            unsigned d = sb + (unsigned)(comp * 8192 + row * 128 + ((seg ^ (row & 7)) << 4));
            cp16(d, ok ? (const void*)s : (const void*)g_qsp[0], ok ? 16 : 0);
        }
    cp_commit();

    float ore[8][4], oim[8][4];
#pragma unroll
    for (int nt = 0; nt < 8; nt++)
#pragma unroll
        for (int c = 0; c < 4; c++) { ore[nt][c] = 0.0f; oim[nt][c] = 0.0f; }
    float d0 = 0.0f, d1 = 0.0f;

    for (int yt = 0; yt < 9; yt++) {
        int y0 = yt << 6;
        // K + V tiles for this yt
#pragma unroll
        for (int comp = 0; comp < 4; comp++)
#pragma unroll
            for (int i = 0; i < 4; i++) {
                int idx = tid + (i << 7);
                int row = idx >> 3, seg = idx & 7;
                int ok = (y0 + row) < 513;
                const __nv_bfloat16* s = g_ksp[comp] + qkb + (size_t)(y0 + row) * 64 + seg * 8;
                unsigned d = sb + (unsigned)(32768 + comp * 8192 + row * 128 + ((seg ^ (row & 7)) << 4));
                cp16(d, ok ? (const void*)s : (const void*)g_ksp[0], ok ? 16 : 0);
                const __nv_bfloat16* sv = g_vsp[comp] + vb + (size_t)row * 576 + y0 + seg * 8;
                unsigned dv = sb + (unsigned)(65536 + comp * 8192 + row * 128 + ((seg ^ (row & 7)) << 4));
                cp16(dv, sv, 16);
            }
        cp_commit();
        cp_wait<0>();
        __syncthreads();

        // ---- GEMM1: S = Q . conj(K)^T over e ----
        float sre[8][4], sim[8][4];
#pragma unroll
        for (int nt = 0; nt < 8; nt++)
#pragma unroll
            for (int c = 0; c < 4; c++) { sre[nt][c] = 0.0f; sim[nt][c] = 0.0f; }

#pragma unroll
        for (int ks = 0; ks < 4; ks++) {
            unsigned qf[4][4], qn0[4], qn1[4];
            int rowA = (w << 4) + (lane & 15);
            int segA = (ks << 1) + (lane >> 4);
            unsigned ab = sb + (unsigned)(rowA * 128 + ((segA ^ (rowA & 7)) << 4));
#pragma unroll
            for (int comp = 0; comp < 4; comp++) ldmx4(qf[comp], ab + comp * 8192u);
#pragma unroll
            for (int r = 0; r < 4; r++) {
                qn0[r] = qf[0][r] ^ 0x80008000u;     // -qr hi
                qn1[r] = qf[1][r] ^ 0x80008000u;     // -qr lo
            }
#pragma unroll
            for (int np = 0; np < 4; np++) {
                int rowB = (np << 4) + ((lane >> 4) << 3) + (lane & 7);
                int segB = (ks << 1) + ((lane >> 3) & 1);
                unsigned bb = sb + 32768u
                    + (unsigned)(rowB * 128 + ((segB ^ (rowB & 7)) << 4));
                unsigned kf[4][4];
#pragma unroll
                for (int comp = 0; comp < 4; comp++) ldmx4(kf[comp], bb + comp * 8192u);
#pragma unroll
                for (int hf = 0; hf < 2; hf++) {
                    int nt = np * 2 + hf;
                    unsigned krh0 = kf[0][hf * 2], krh1 = kf[0][hf * 2 + 1];
                    unsigned krl0 = kf[1][hf * 2], krl1 = kf[1][hf * 2 + 1];
                    unsigned kih0 = kf[2][hf * 2], kih1 = kf[2][hf * 2 + 1];
                    unsigned kil0 = kf[3][hf * 2], kil1 = kf[3][hf * 2 + 1];
                    // sre += qr.kr + qi.ki  (3-term each)
                    mma4(sre[nt], qf[0], krh0, krh1);
                    mma4(sre[nt], qf[0], krl0, krl1);
                    mma4(sre[nt], qf[1], krh0, krh1);
                    mma4(sre[nt], qf[2], kih0, kih1);
                    mma4(sre[nt], qf[2], kil0, kil1);
                    mma4(sre[nt], qf[3], kih0, kih1);
                    // sim += qi.kr - qr.ki
                    mma4(sim[nt], qf[2], krh0, krh1);
                    mma4(sim[nt], qf[2], krl0, krl1);
                    mma4(sim[nt], qf[3], krh0, krh1);
                    mma4(sim[nt], qn0,   kih0, kih1);
                    mma4(sim[nt], qn0,   kil0, kil1);
                    mma4(sim[nt], qn1,   kih0, kih1);
                }
            }
        }

        // ---- epilogue + GEMM2, per y-16 block (T register-resident) ----
#pragma unroll
        for (int kb = 0; kb < 4; kb++) {
            unsigned trh[4], trl[4], tih[4], til[4];
#pragma unroll
            for (int hf = 0; hf < 2; hf++) {       // nt0 -> a0,a1; nt1 -> a2,a3
                int nt = kb * 2 + hf;
                float tr[4], ti[4];
#pragma unroll
                for (int c = 0; c < 4; c++) {
                    float sr = sre[nt][c] * 0.125f;
                    float si = sim[nt][c] * 0.125f;
                    float mg = sqrtf(sr * sr + si * si);
                    float wt = 1.0f + sigmoidf_(mg);
                    float mw = mg * wt;
                    if (c < 2) d0 += mw; else d1 += mw;
                    tr[c] = sr * wt;
                    ti[c] = si * wt;
                }
                split2(tr[0], tr[1], trh[hf * 2], trl[hf * 2]);
                split2(tr[2], tr[3], trh[hf * 2 + 1], trl[hf * 2 + 1]);
                split2(ti[0], ti[1], tih[hf * 2], til[hf * 2]);
                split2(ti[2], ti[3], tih[hf * 2 + 1], til[hf * 2 + 1]);
            }
            unsigned tnh[4], tnl[4];
#pragma unroll
            for (int r = 0; r < 4; r++) {
                tnh[r] = tih[r] ^ 0x80008000u;
                tnl[r] = til[r] ^ 0x80008000u;
            }
            // GEMM2 k-step kb: of[x, e] += T . V^T (V[e][y])
#pragma unroll
            for (int np = 0; np < 4; np++) {
                int rowB = (np << 4) + ((lane >> 4) << 3) + (lane & 7);
                int segB = (kb << 1) + ((lane >> 3) & 1);
                unsigned bb = sb + 65536u
                    + (unsigned)(rowB * 128 + ((segB ^ (rowB & 7)) << 4));
                unsigned vf[4][4];
#pragma unroll
                for (int comp = 0; comp < 4; comp++) ldmx4(vf[comp], bb + comp * 8192u);
#pragma unroll
                for (int hf = 0; hf < 2; hf++) {
                    int nt = np * 2 + hf;
                    unsigned vrh0 = vf[0][hf * 2], vrh1 = vf[0][hf * 2 + 1];
                    unsigned vrl0 = vf[1][hf * 2], vrl1 = vf[1][hf * 2 + 1];
                    unsigned vih0 = vf[2][hf * 2], vih1 = vf[2][hf * 2 + 1];
                    unsigned vil0 = vf[3][hf * 2], vil1 = vf[3][hf * 2 + 1];
                    // ore += tr.vr - ti.vi
                    mma4(ore[nt], trh, vrh0, vrh1);
                    mma4(ore[nt], trh, vrl0, vrl1);
                    mma4(ore[nt], trl, vrh0, vrh1);
                    mma4(ore[nt], tnh, vih0, vih1);
                    mma4(ore[nt], tnh, vil0, vil1);
                    mma4(ore[nt], tnl, vih0, vih1);
                    // oim += tr.vi + ti.vr
                    mma4(oim[nt], trh, vih0, vih1);
                    mma4(oim[nt], trh, vil0, vil1);
                    mma4(oim[nt], trl, vih0, vih1);
                    mma4(oim[nt], tih, vrh0, vrh1);
                    mma4(oim[nt], tih, vrl0, vrl1);
                    mma4(oim[nt], til, vrh0, vrh1);
                }
            }
        }
        __syncthreads();   // V/K reads done before next yt's loads
    }

    // D row-sum across quad (cols live in lane&3)
    d0 += __shfl_xor_sync(0xffffffffu, d0, 1);
    d0 += __shfl_xor_sync(0xffffffffu, d0, 2);
    d1 += __shfl_xor_sync(0xffffffffu, d1, 1);
    d1 += __shfl_xor_sync(0xffffffffu, d1, 2);
    d0 = 1.0f / fmaxf(d0, 1e-12f);
    d1 = 1.0f / fmaxf(d1, 1e-12f);

    int xr = x0 + (w << 4) + (lane >> 2);
    int ec = (lane & 3) << 1;
#pragma unroll
    for (int nt = 0; nt < 8; nt++) {
        int e = (nt << 3) + ec;
        if (xr < 513) {
            g_of_re[obase + (size_t)e * 513 + xr]       = ore[nt][0] * d0;
            g_of_re[obase + (size_t)(e + 1) * 513 + xr] = ore[nt][1] * d0;
            g_of_im[obase + (size_t)e * 513 + xr]       = oim[nt][0] * d0;
            g_of_im[obase + (size_t)(e + 1) * 513 + xr] = oim[nt][1] * d0;
        }
        if (xr + 8 < 513) {
            g_of_re[obase + (size_t)e * 513 + xr + 8]       = ore[nt][2] * d1;
            g_of_re[obase + (size_t)(e + 1) * 513 + xr + 8] = ore[nt][3] * d1;
            g_of_im[obase + (size_t)e * 513 + xr + 8]       = oim[nt][2] * d1;
            g_of_im[obase + (size_t)(e + 1) * 513 + xr + 8] = oim[nt][3] * d1;
        }
    }
}

// ---------------- irfft (ortho) + scatter to out[b,l,h,e] ------------------
__global__ __launch_bounds__(256) void irfft_kernel(float* __restrict__ out) {
    __shared__ float2 bufA[1024];
    __shared__ float2 bufB[1024];
    int row = blockIdx.x, tid = threadIdx.x;
    const float* pr = g_of_re + (size_t)row * 513;
    const float* pi = g_of_im + (size_t)row * 513;
    for (int i = tid; i < 1024; i += 256) {
        float re, im;
        if (i < 513) { re = pr[i];        im =  pi[i]; }
        else         { re = pr[1024 - i]; im = -pi[1024 - i]; }
        bufA[i] = make_float2(re, im);
    }
    __syncthreads();
    fft1024_shared(bufA, bufB, 1.0f, tid);
    int b = row >> 9, c = row & 511;
    float* po = out + (size_t)b * 524288 + c;
    for (int i = tid; i < 1024; i += 256)
        po[(size_t)i * 512] = bufA[i].x * 0.03125f;
}

// ---------------- launch ---------------------------------------------------
extern "C" void kernel_launch(void* const* d_in, const int* in_sizes, int n_in,
                              void* d_out, int out_size) {
    const float* q    = (const float*)d_in[0];
    const float* k    = (const float*)d_in[1];
    const float* v    = (const float*)d_in[2];
    const float* W    = (const float*)d_in[3];
    const float* bias = (const float*)d_in[4];
    float* out = (float*)d_out;

    const int conv_smem = 49152;
    cudaFuncSetAttribute(conv_mma_kernel,
                         cudaFuncAttributeMaxDynamicSharedMemorySize, conv_smem);
    const int attn_smem = 98304;
    cudaFuncSetAttribute(attn_kernel,
                         cudaFuncAttributeMaxDynamicSharedMemorySize, attn_smem);

    init_all_kernel<<<104448, 256>>>(W, q);     // (1024+16384)*1536 / 256
    conv_mma_kernel<<<dim3(16, 128), 256, conv_smem>>>(bias);
    rfft_all_kernel<<<dim3(NROW, 3), 256>>>(k, v);
    attn_kernel<<<dim3(9, 128), 128, attn_smem>>>();   // ncu slot (4th)
    irfft_kernel<<<NROW, 256>>>(out);
}